// round 2
// baseline (speedup 1.0000x reference)
#include <cuda_runtime.h>
#include <cuda_bf16.h>
#include <cstddef>
#include <math.h>

// ---------------------------------------------------------------------------
// VQ-VAE forward, fp32, GB300 sm_103a. Arithmetic replicates the JAX fp32
// reference closely (bias-after-accumulate, unfused z^2 sums, sequential
// k-ascending dot chains, fp32 straight-through) to avoid VQ argmin flips.
// ---------------------------------------------------------------------------

#define NB 32          // batch

__device__ float g_A[32u*64u*128u*128u];   // h1 / deconv1 out
__device__ float g_B[32u*128u*64u*64u];    // h2 / decoder trunk
__device__ float g_C[32u*128u*64u*64u];    // encoder trunk
__device__ float g_T[32u*32u*64u*64u];     // res hidden
__device__ float g_Z[32u*64u*64u*64u];     // z
__device__ float g_Q[32u*64u*64u*64u];     // straight-through quantized
__device__ float g_CN[512];                // codebook norms (fp32, ref-order)
__device__ double g_LOSS;

// ---------------------------------------------------------------------------
// conv 3x3, stride 1, pad 1, H=W=64. Tile 32x32, thread: 2x2 px, 4 co.
// Accumulate from 0 (ci,ky,kx ascending), bias added at the end.
// ---------------------------------------------------------------------------
template<int CIN, int COUT, bool RELU_IN>
__global__ void __launch_bounds__(256) conv3_k(const float* __restrict__ in,
                                               const float* __restrict__ w,
                                               const float* __restrict__ b,
                                               float* __restrict__ out)
{
    constexpr int COG = COUT / 4;
    __shared__ float s_in[34][35];
    __shared__ float s_w[4][CIN][9];

    const int tid = threadIdx.x;
    const int tx = tid & 15, ty = tid >> 4;
    const int x0 = blockIdx.x * 32, y0 = blockIdx.y * 32;
    const int n  = blockIdx.z / COG;
    const int cg = blockIdx.z % COG;

    for (int i = tid; i < 4 * CIN * 9; i += 256) {
        int co = i / (CIN * 9), r = i % (CIN * 9);
        s_w[co][r / 9][r % 9] = w[(size_t)(cg * 4 + co) * CIN * 9 + r];
    }

    float acc[2][2][4];
    #pragma unroll
    for (int py = 0; py < 2; py++)
        #pragma unroll
        for (int px = 0; px < 2; px++)
            #pragma unroll
            for (int co = 0; co < 4; co++)
                acc[py][px][co] = 0.f;

    const float* ip = in + (size_t)n * CIN * 4096;
    for (int ci = 0; ci < CIN; ci++) {
        __syncthreads();
        const float* p = ip + (size_t)ci * 4096;
        for (int i = tid; i < 34 * 34; i += 256) {
            int yy = i / 34, xx = i % 34;
            int gy = y0 - 1 + yy, gx = x0 - 1 + xx;
            float v = 0.f;
            if ((unsigned)gy < 64u && (unsigned)gx < 64u) v = p[gy * 64 + gx];
            if (RELU_IN) v = fmaxf(v, 0.f);
            s_in[yy][xx] = v;
        }
        __syncthreads();
        #pragma unroll
        for (int py = 0; py < 2; py++)
            #pragma unroll
            for (int px = 0; px < 2; px++) {
                const int ly = ty + 16 * py, lx = tx + 16 * px;
                #pragma unroll
                for (int ky = 0; ky < 3; ky++)
                    #pragma unroll
                    for (int kx = 0; kx < 3; kx++) {
                        float v = s_in[ly + ky][lx + kx];
                        #pragma unroll
                        for (int co = 0; co < 4; co++)
                            acc[py][px][co] = fmaf(v, s_w[co][ci][ky * 3 + kx], acc[py][px][co]);
                    }
            }
    }

    #pragma unroll
    for (int co = 0; co < 4; co++) {
        float bias = b[cg * 4 + co];
        float* op = out + ((size_t)n * COUT + cg * 4 + co) * 4096;
        #pragma unroll
        for (int py = 0; py < 2; py++)
            #pragma unroll
            for (int px = 0; px < 2; px++)
                op[(y0 + ty + 16 * py) * 64 + x0 + tx + 16 * px] =
                    __fadd_rn(acc[py][px][co], bias);
    }
}

// ---------------------------------------------------------------------------
// conv 4x4, stride 2, pad 1. Tile 32x32 out, thread: 2x2 px, 4 co.
// ---------------------------------------------------------------------------
template<int CIN, int COUT, int HOUT, bool RELU_OUT>
__global__ void __launch_bounds__(256) conv4s2_k(const float* __restrict__ in,
                                                 const float* __restrict__ w,
                                                 const float* __restrict__ b,
                                                 float* __restrict__ out)
{
    constexpr int HIN = HOUT * 2;
    constexpr int COG = COUT / 4;
    __shared__ float s_in[66][67];
    __shared__ float s_w[4][CIN][16];

    const int tid = threadIdx.x;
    const int tx = tid & 15, ty = tid >> 4;
    const int x0 = blockIdx.x * 32, y0 = blockIdx.y * 32;
    const int n  = blockIdx.z / COG;
    const int cg = blockIdx.z % COG;

    for (int i = tid; i < 4 * CIN * 16; i += 256) {
        int co = i / (CIN * 16), r = i % (CIN * 16);
        s_w[co][r / 16][r % 16] = w[(size_t)(cg * 4 + co) * CIN * 16 + r];
    }

    float acc[2][2][4];
    #pragma unroll
    for (int py = 0; py < 2; py++)
        #pragma unroll
        for (int px = 0; px < 2; px++)
            #pragma unroll
            for (int co = 0; co < 4; co++)
                acc[py][px][co] = 0.f;

    const float* ip = in + (size_t)n * CIN * HIN * HIN;
    for (int ci = 0; ci < CIN; ci++) {
        __syncthreads();
        const float* p = ip + (size_t)ci * HIN * HIN;
        for (int i = tid; i < 66 * 66; i += 256) {
            int yy = i / 66, xx = i % 66;
            int gy = 2 * y0 - 1 + yy, gx = 2 * x0 - 1 + xx;
            float v = 0.f;
            if ((unsigned)gy < (unsigned)HIN && (unsigned)gx < (unsigned)HIN)
                v = p[gy * HIN + gx];
            s_in[yy][xx] = v;
        }
        __syncthreads();
        #pragma unroll
        for (int py = 0; py < 2; py++)
            #pragma unroll
            for (int px = 0; px < 2; px++) {
                const int ly = ty + 16 * py, lx = tx + 16 * px;
                #pragma unroll
                for (int ky = 0; ky < 4; ky++)
                    #pragma unroll
                    for (int kx = 0; kx < 4; kx++) {
                        float v = s_in[2 * ly + ky][2 * lx + kx];
                        #pragma unroll
                        for (int co = 0; co < 4; co++)
                            acc[py][px][co] = fmaf(v, s_w[co][ci][ky * 4 + kx], acc[py][px][co]);
                    }
            }
    }

    #pragma unroll
    for (int co = 0; co < 4; co++) {
        float bias = b[cg * 4 + co];
        float* op = out + ((size_t)n * COUT + cg * 4 + co) * HOUT * HOUT;
        #pragma unroll
        for (int py = 0; py < 2; py++)
            #pragma unroll
            for (int px = 0; px < 2; px++) {
                float v = __fadd_rn(acc[py][px][co], bias);
                if (RELU_OUT) v = fmaxf(v, 0.f);
                op[(y0 + ty + 16 * py) * HOUT + x0 + tx + 16 * px] = v;
            }
    }
}

// ---------------------------------------------------------------------------
// conv 1x1 at 64x64. 8 co per thread. Optional residual add (out = resid + h).
// ---------------------------------------------------------------------------
template<int CIN, int COUT, bool RELU_IN, bool RESID>
__global__ void __launch_bounds__(256) conv1x1_k(const float* __restrict__ in,
                                                 const float* __restrict__ w,
                                                 const float* __restrict__ b,
                                                 float* __restrict__ out,
                                                 const float* __restrict__ resid)
{
    constexpr int COG = COUT / 8;
    __shared__ float s_w[8][CIN];
    const int tid = threadIdx.x;
    const int n  = blockIdx.z / COG;
    const int cg = blockIdx.z % COG;

    for (int i = tid; i < 8 * CIN; i += 256)
        s_w[i / CIN][i % CIN] = w[(size_t)(cg * 8 + i / CIN) * CIN + i % CIN];
    __syncthreads();

    const int px = blockIdx.x * 256 + tid;
    const float* ip = in + (size_t)n * CIN * 4096 + px;

    float acc[8];
    #pragma unroll
    for (int co = 0; co < 8; co++) acc[co] = 0.f;

    #pragma unroll 4
    for (int ci = 0; ci < CIN; ci++) {
        float v = ip[(size_t)ci * 4096];
        if (RELU_IN) v = fmaxf(v, 0.f);
        #pragma unroll
        for (int co = 0; co < 8; co++)
            acc[co] = fmaf(v, s_w[co][ci], acc[co]);
    }

    const size_t ob = ((size_t)n * COUT + cg * 8) * 4096 + px;
    #pragma unroll
    for (int co = 0; co < 8; co++) {
        float h = __fadd_rn(acc[co], b[cg * 8 + co]);   // conv + bias
        float r = h;
        if (RESID) r = __fadd_rn(resid[ob + (size_t)co * 4096], h);  // x + h
        out[ob + (size_t)co * 4096] = r;
    }
}

// ---------------------------------------------------------------------------
// Transposed conv k=4 s=2 p=1 (gather). Weight (Cin, Cout, 4, 4).
// ACT: 0 none, 1 relu, 2 tanh.
// ---------------------------------------------------------------------------
template<int CIN, int COUT, int CO_T, int HIN, bool RELU_IN, int ACT>
__global__ void __launch_bounds__(256) deconv_k(const float* __restrict__ in,
                                                const float* __restrict__ w,
                                                const float* __restrict__ b,
                                                float* __restrict__ out)
{
    constexpr int HOUT = HIN * 2;
    constexpr int COG = COUT / CO_T;
    __shared__ float s_in[18][19];
    __shared__ float s_w[CO_T][CIN][16];

    const int tid = threadIdx.x;
    const int tx = tid & 15, ty = tid >> 4;
    const int x0 = blockIdx.x * 32, y0 = blockIdx.y * 32;
    const int n  = blockIdx.z / COG;
    const int cg = blockIdx.z % COG;

    for (int i = tid; i < CO_T * CIN * 16; i += 256) {
        int co = i / (CIN * 16), r = i % (CIN * 16);
        int ci = r / 16, k = r % 16;
        s_w[co][ci][k] = w[((size_t)ci * COUT + cg * CO_T + co) * 16 + k];
    }

    float acc[2][2][CO_T];
    #pragma unroll
    for (int py = 0; py < 2; py++)
        #pragma unroll
        for (int px = 0; px < 2; px++)
            #pragma unroll
            for (int co = 0; co < CO_T; co++)
                acc[py][px][co] = 0.f;

    const int iyb = y0 / 2 - 1, ixb = x0 / 2 - 1;
    const float* ip = in + (size_t)n * CIN * HIN * HIN;

    for (int ci = 0; ci < CIN; ci++) {
        __syncthreads();
        const float* p = ip + (size_t)ci * HIN * HIN;
        for (int i = tid; i < 18 * 18; i += 256) {
            int yy = i / 18, xx = i % 18;
            int gy = iyb + yy, gx = ixb + xx;
            float v = 0.f;
            if ((unsigned)gy < (unsigned)HIN && (unsigned)gx < (unsigned)HIN)
                v = p[gy * HIN + gx];
            if (RELU_IN) v = fmaxf(v, 0.f);
            s_in[yy][xx] = v;
        }
        __syncthreads();
        #pragma unroll
        for (int py = 0; py < 2; py++)
            #pragma unroll
            for (int px = 0; px < 2; px++) {
                const int ly = ty + 16 * py, lx = tx + 16 * px;
                const int ky0 = (ly + 1) & 1, kx0 = (lx + 1) & 1;
                #pragma unroll
                for (int a = 0; a < 2; a++) {
                    const int ky = ky0 + 2 * a;
                    const int iyl = ((ly + 1 - ky) >> 1) + 1;
                    #pragma unroll
                    for (int c2 = 0; c2 < 2; c2++) {
                        const int kx = kx0 + 2 * c2;
                        const int ixl = ((lx + 1 - kx) >> 1) + 1;
                        float v = s_in[iyl][ixl];
                        #pragma unroll
                        for (int co = 0; co < CO_T; co++)
                            acc[py][px][co] = fmaf(v, s_w[co][ci][ky * 4 + kx], acc[py][px][co]);
                    }
                }
            }
    }

    #pragma unroll
    for (int co = 0; co < CO_T; co++) {
        float bias = b[cg * CO_T + co];
        float* op = out + ((size_t)n * COUT + cg * CO_T + co) * HOUT * HOUT;
        #pragma unroll
        for (int py = 0; py < 2; py++)
            #pragma unroll
            for (int px = 0; px < 2; px++) {
                float v = __fadd_rn(acc[py][px][co], bias);
                if (ACT == 1) v = fmaxf(v, 0.f);
                if (ACT == 2) v = tanhf(v);
                op[(y0 + ty + 16 * py) * HOUT + x0 + tx + 16 * px] = v;
            }
    }
}

// ---------------------------------------------------------------------------
// Codebook norms: ||c||^2 replicating sum(c**2): square (rounded), then
// sequential adds in ascending d. No FMA contraction.
// ---------------------------------------------------------------------------
__global__ void cnorm_k(const float* __restrict__ cb, float* __restrict__ cn)
{
    int c = blockIdx.x * 256 + threadIdx.x;
    if (c < 512) {
        float s = 0.f;
        for (int d = 0; d < 64; d++) {
            float v = cb[c * 64 + d];
            s = __fadd_rn(s, __fmul_rn(v, v));
        }
        cn[c] = s;
    }
}

__global__ void zero_loss_k(double* loss) { *loss = 0.0; }

// ---------------------------------------------------------------------------
// VQ: replicate reference fp32 arithmetic.
//   sumz2 = sequential unfused sum of z[d]^2
//   dot   = sequential d-ascending single-accumulator FMA chain (cublas-like)
//   dist  = fl(fl(sumz2 - 2*dot) + cnorm), argmin first-min-wins
//   output = straight-through z + (q - z) in fp32
// ---------------------------------------------------------------------------
__global__ void __launch_bounds__(256) vq_k(const float* __restrict__ z,
                                            const float* __restrict__ cb,
                                            const float* __restrict__ cn,
                                            float* __restrict__ q,
                                            double* __restrict__ loss)
{
    __shared__ float s_cT[64][128];   // transposed codebook chunk: [d][c]
    __shared__ float s_n[128];
    __shared__ double s_red[256];

    const int tid = threadIdx.x;
    const int vec = blockIdx.x * 256 + tid;           // 131072 total
    const int n = vec >> 12, px = vec & 4095;
    const float* zp = z + (size_t)n * 64 * 4096 + px;

    float zr[64];
    #pragma unroll
    for (int d = 0; d < 64; d++) zr[d] = zp[(size_t)d * 4096];

    // sum(z^2): unfused, sequential ascending d
    float sumz2 = 0.f;
    #pragma unroll
    for (int d = 0; d < 64; d++)
        sumz2 = __fadd_rn(sumz2, __fmul_rn(zr[d], zr[d]));

    float best = 3.4e38f;
    int bi = 0;

    for (int ch = 0; ch < 4; ch++) {
        __syncthreads();
        // load chunk of 128 codes, transposed
        for (int i = tid; i < 128 * 64; i += 256) {
            int c = i >> 6, d = i & 63;
            s_cT[d][c] = cb[(size_t)(ch * 128 + c) * 64 + d];
        }
        if (tid < 128) s_n[tid] = cn[ch * 128 + tid];
        __syncthreads();

        for (int c0 = 0; c0 < 128; c0 += 4) {
            float a0 = 0.f, a1 = 0.f, a2 = 0.f, a3 = 0.f;
            #pragma unroll
            for (int d = 0; d < 64; d++) {
                float4 cv = *(const float4*)&s_cT[d][c0];
                a0 = fmaf(zr[d], cv.x, a0);
                a1 = fmaf(zr[d], cv.y, a1);
                a2 = fmaf(zr[d], cv.z, a2);
                a3 = fmaf(zr[d], cv.w, a3);
            }
            // dist = (sumz2 - 2*dot) + cnorm, each step fp32-rounded.
            // (2*dot is exact; fma contraction of the subtract is bit-identical)
            float t0 = __fadd_rn(sumz2, -2.f * a0);
            float t1 = __fadd_rn(sumz2, -2.f * a1);
            float t2 = __fadd_rn(sumz2, -2.f * a2);
            float t3 = __fadd_rn(sumz2, -2.f * a3);
            float d0 = __fadd_rn(t0, s_n[c0 + 0]);
            float d1 = __fadd_rn(t1, s_n[c0 + 1]);
            float d2 = __fadd_rn(t2, s_n[c0 + 2]);
            float d3 = __fadd_rn(t3, s_n[c0 + 3]);
            int cb0 = ch * 128 + c0;
            if (d0 < best) { best = d0; bi = cb0 + 0; }
            if (d1 < best) { best = d1; bi = cb0 + 1; }
            if (d2 < best) { best = d2; bi = cb0 + 2; }
            if (d3 < best) { best = d3; bi = cb0 + 3; }
        }
    }

    const float* cp = cb + (size_t)bi * 64;
    float* qp = q + (size_t)n * 64 * 4096 + px;
    double sum = 0.0;
    #pragma unroll
    for (int d = 0; d < 64; d++) {
        float qv = __ldg(cp + d);
        float df = __fadd_rn(qv, -zr[d]);          // quantized - z (fp32)
        sum += (double)df * (double)df;            // loss term (pre straight-through)
        qp[(size_t)d * 4096] = __fadd_rn(zr[d], df);  // z + (q - z) straight-through
    }

    s_red[tid] = sum;
    __syncthreads();
    for (int s = 128; s > 0; s >>= 1) {
        if (tid < s) s_red[tid] += s_red[tid + s];
        __syncthreads();
    }
    if (tid == 0) atomicAdd(loss, s_red[0]);
}

__global__ void finalize_k(const double* __restrict__ loss, float* __restrict__ out, int idx)
{
    out[idx] = (float)((*loss) * 1.25 / 8388608.0);   // (1 + 0.25) * mean
}

// ---------------------------------------------------------------------------
// Host orchestration
// ---------------------------------------------------------------------------
extern "C" void kernel_launch(void* const* d_in, const int* in_sizes, int n_in,
                              void* d_out, int out_size)
{
    const float* x    = (const float*)d_in[0];
    const float* ew1  = (const float*)d_in[1];
    const float* eb1  = (const float*)d_in[2];
    const float* ew2  = (const float*)d_in[3];
    const float* eb2  = (const float*)d_in[4];
    const float* ew3  = (const float*)d_in[5];
    const float* eb3  = (const float*)d_in[6];
    const float* erw1 = (const float*)d_in[7];
    const float* erb1 = (const float*)d_in[8];
    const float* erw2 = (const float*)d_in[9];
    const float* erb2 = (const float*)d_in[10];
    const float* pvqw = (const float*)d_in[11];
    const float* pvqb = (const float*)d_in[12];
    const float* cb   = (const float*)d_in[13];
    const float* dw1  = (const float*)d_in[14];
    const float* db1  = (const float*)d_in[15];
    const float* drw1 = (const float*)d_in[16];
    const float* drb1 = (const float*)d_in[17];
    const float* drw2 = (const float*)d_in[18];
    const float* drb2 = (const float*)d_in[19];
    const float* t1w  = (const float*)d_in[20];
    const float* t1b  = (const float*)d_in[21];
    const float* t2w  = (const float*)d_in[22];
    const float* t2b  = (const float*)d_in[23];
    float* out = (float*)d_out;

    float *A, *B, *C, *T, *Z, *Q, *CN;
    double* L;
    cudaGetSymbolAddress((void**)&A, g_A);
    cudaGetSymbolAddress((void**)&B, g_B);
    cudaGetSymbolAddress((void**)&C, g_C);
    cudaGetSymbolAddress((void**)&T, g_T);
    cudaGetSymbolAddress((void**)&Z, g_Z);
    cudaGetSymbolAddress((void**)&Q, g_Q);
    cudaGetSymbolAddress((void**)&CN, g_CN);
    cudaGetSymbolAddress((void**)&L, g_LOSS);

    // Encoder
    conv4s2_k<3, 64, 128, true><<<dim3(4, 4, NB * 16), 256>>>(x, ew1, eb1, A);
    conv4s2_k<64, 128, 64, true><<<dim3(2, 2, NB * 32), 256>>>(A, ew2, eb2, B);
    conv3_k<128, 128, false><<<dim3(2, 2, NB * 32), 256>>>(B, ew3, eb3, C);
    for (int i = 0; i < 2; i++) {
        conv3_k<128, 32, true><<<dim3(2, 2, NB * 8), 256>>>(
            C, erw1 + (size_t)i * 32 * 128 * 9, erb1 + i * 32, T);
        conv1x1_k<32, 128, true, true><<<dim3(16, 1, NB * 16), 256>>>(
            T, erw2 + (size_t)i * 128 * 32, erb2 + i * 128, C, C);
    }
    // pre-VQ 1x1 (absorbs res_stack's final relu)
    conv1x1_k<128, 64, true, false><<<dim3(16, 1, NB * 8), 256>>>(C, pvqw, pvqb, Z, nullptr);

    // VQ
    zero_loss_k<<<1, 1>>>(L);
    cnorm_k<<<2, 256>>>(cb, CN);
    vq_k<<<512, 256>>>(Z, cb, CN, Q, L);

    // Decoder
    conv3_k<64, 128, false><<<dim3(2, 2, NB * 32), 256>>>(Q, dw1, db1, B);
    for (int i = 0; i < 2; i++) {
        conv3_k<128, 32, true><<<dim3(2, 2, NB * 8), 256>>>(
            B, drw1 + (size_t)i * 32 * 128 * 9, drb1 + i * 32, T);
        conv1x1_k<32, 128, true, true><<<dim3(16, 1, NB * 16), 256>>>(
            T, drw2 + (size_t)i * 128 * 32, drb2 + i * 128, B, B);
    }
    // deconv1 absorbs res_stack's final relu on input, relu on output
    deconv_k<128, 64, 4, 64, true, 1><<<dim3(4, 4, NB * 16), 256>>>(B, t1w, t1b, A);
    // deconv2 -> tanh, straight to output
    deconv_k<64, 3, 3, 128, false, 2><<<dim3(8, 8, NB), 256>>>(A, t2w, t2b, out);

    // Scalar vq_loss appended after the reconstruction
    if (out_size > 32 * 3 * 256 * 256)
        finalize_k<<<1, 1>>>(L, out, out_size - 1);
}

// round 3
// speedup vs baseline: 1.6710x; 1.6710x over previous
#include <cuda_runtime.h>
#include <cuda_bf16.h>
#include <cstddef>
#include <math.h>

// ---------------------------------------------------------------------------
// VQ-VAE forward, fp32 with packed f32x2 FMA (sm_103a FFMA2), GB300.
// Per-accumulator FMA chain order identical to the R2 passing kernel
// (ci ascending, then tap order), so VQ argmin decisions are unchanged.
// ---------------------------------------------------------------------------

#define NB 32

typedef unsigned long long ull;

__device__ __forceinline__ ull pk2(float v) {
    ull r; asm("mov.b64 %0, {%1, %1};" : "=l"(r) : "f"(v)); return r;
}
__device__ __forceinline__ void fma2(ull& d, ull a, ull b) {
    asm("fma.rn.f32x2 %0, %1, %2, %0;" : "+l"(d) : "l"(a), "l"(b));
}
__device__ __forceinline__ float2 up2(ull v) {
    float2 r; asm("mov.b64 {%0, %1}, %2;" : "=f"(r.x), "=f"(r.y) : "l"(v)); return r;
}

__device__ float g_A[32u*64u*128u*128u];   // h1 / deconv1 out
__device__ float g_B[32u*128u*64u*64u];    // h2 / decoder trunk
__device__ float g_C[32u*128u*64u*64u];    // encoder trunk
__device__ float g_T[32u*32u*64u*64u];     // res hidden
__device__ float g_Z[32u*64u*64u*64u];     // z
__device__ float g_Q[32u*64u*64u*64u];     // straight-through quantized
__device__ float g_CN[512];
__device__ double g_LOSS;

// ---------------------------------------------------------------------------
// conv 3x3 s1 p1 at 64x64, f32x2 packed. Tile 32x32, thread: contiguous
// 2x2 px, 8 cout (4 lane-pairs). ci staged in chunks of 8.
// ---------------------------------------------------------------------------
template<int CIN, int COUT, bool RELU_IN>
__global__ void __launch_bounds__(256) conv3v2_k(const float* __restrict__ in,
                                                 const float* __restrict__ w,
                                                 const float* __restrict__ b,
                                                 float* __restrict__ out)
{
    constexpr int COG = COUT / 8;
    constexpr int CHUNK = 8;
    __shared__ float  s_in[CHUNK][34][36];
    __shared__ float2 s_w[CHUNK][9][4];

    const int tid = threadIdx.x;
    const int tx = tid & 15, ty = tid >> 4;
    const int x0 = blockIdx.x * 32, y0 = blockIdx.y * 32;
    const int n  = blockIdx.z / COG;
    const int cg = blockIdx.z % COG;

    ull acc[2][2][4];
    #pragma unroll
    for (int py = 0; py < 2; py++)
        #pragma unroll
        for (int px = 0; px < 2; px++)
            #pragma unroll
            for (int p = 0; p < 4; p++)
                acc[py][px][p] = 0ull;   // {0.0f, 0.0f}

    const float* ip = in + (size_t)n * CIN * 4096;

    #pragma unroll 1
    for (int cc = 0; cc < CIN; cc += CHUNK) {
        __syncthreads();
        // stage weight pairs for this ci chunk: pair p -> (co 2p, co 2p+1)
        for (int i = tid; i < CHUNK * 9 * 4; i += 256) {
            int ci = i / 36, r = i % 36, k = r / 4, p = r % 4;
            const float* wp = w + ((size_t)(cg * 8 + 2 * p) * CIN + cc + ci) * 9 + k;
            s_w[ci][k][p] = make_float2(wp[0], wp[CIN * 9]);
        }
        // stage input planes
        for (int i = tid; i < CHUNK * 34 * 34; i += 256) {
            int ci = i / 1156, r = i % 1156, yy = r / 34, xx = r % 34;
            int gy = y0 - 1 + yy, gx = x0 - 1 + xx;
            float v = 0.f;
            if ((unsigned)gy < 64u && (unsigned)gx < 64u)
                v = ip[(size_t)(cc + ci) * 4096 + gy * 64 + gx];
            if (RELU_IN) v = fmaxf(v, 0.f);
            s_in[ci][yy][xx] = v;
        }
        __syncthreads();

        #pragma unroll 1
        for (int ci = 0; ci < CHUNK; ci++) {
            ull iv[4][4];
            #pragma unroll
            for (int r = 0; r < 4; r++)
                #pragma unroll
                for (int c = 0; c < 4; c++)
                    iv[r][c] = pk2(s_in[ci][2 * ty + r][2 * tx + c]);

            #pragma unroll
            for (int k = 0; k < 9; k++) {
                const int ky = k / 3, kx = k % 3;
                const ull* wq = reinterpret_cast<const ull*>(&s_w[ci][k][0]);
                ull wv0 = wq[0], wv1 = wq[1], wv2 = wq[2], wv3 = wq[3];
                #pragma unroll
                for (int py = 0; py < 2; py++)
                    #pragma unroll
                    for (int px = 0; px < 2; px++) {
                        ull inp = iv[py + ky][px + kx];
                        fma2(acc[py][px][0], inp, wv0);
                        fma2(acc[py][px][1], inp, wv1);
                        fma2(acc[py][px][2], inp, wv2);
                        fma2(acc[py][px][3], inp, wv3);
                    }
            }
        }
    }

    #pragma unroll
    for (int p = 0; p < 4; p++) {
        const int co = cg * 8 + 2 * p;
        const float b0 = b[co], b1 = b[co + 1];
        float* o0 = out + ((size_t)n * COUT + co) * 4096;
        float* o1 = o0 + 4096;
        #pragma unroll
        for (int py = 0; py < 2; py++)
            #pragma unroll
            for (int px = 0; px < 2; px++) {
                float2 v = up2(acc[py][px][p]);
                int off = (y0 + 2 * ty + py) * 64 + x0 + 2 * tx + px;
                o0[off] = __fadd_rn(v.x, b0);
                o1[off] = __fadd_rn(v.y, b1);
            }
    }
}

// ---------------------------------------------------------------------------
// conv 4x4 s2 p1 (64->128ch, out 64x64), f32x2. Tile 32x32 out, thread:
// contiguous 2x2 px, 8 cout. ci chunks of 2 (66x66 staging is large).
// ---------------------------------------------------------------------------
template<int CIN, int COUT, int HOUT, bool RELU_OUT>
__global__ void __launch_bounds__(256) conv4v2_k(const float* __restrict__ in,
                                                 const float* __restrict__ w,
                                                 const float* __restrict__ b,
                                                 float* __restrict__ out)
{
    constexpr int HIN = HOUT * 2;
    constexpr int COG = COUT / 8;
    constexpr int CHUNK = 2;
    __shared__ float  s_in[CHUNK][66][68];
    __shared__ float2 s_w[CHUNK][16][4];

    const int tid = threadIdx.x;
    const int tx = tid & 15, ty = tid >> 4;
    const int x0 = blockIdx.x * 32, y0 = blockIdx.y * 32;
    const int n  = blockIdx.z / COG;
    const int cg = blockIdx.z % COG;

    ull acc[2][2][4];
    #pragma unroll
    for (int py = 0; py < 2; py++)
        #pragma unroll
        for (int px = 0; px < 2; px++)
            #pragma unroll
            for (int p = 0; p < 4; p++)
                acc[py][px][p] = 0ull;

    const float* ip = in + (size_t)n * CIN * HIN * HIN;

    #pragma unroll 1
    for (int cc = 0; cc < CIN; cc += CHUNK) {
        __syncthreads();
        for (int i = tid; i < CHUNK * 16 * 4; i += 256) {
            int ci = i / 64, r = i % 64, k = r / 4, p = r % 4;
            const float* wp = w + ((size_t)(cg * 8 + 2 * p) * CIN + cc + ci) * 16 + k;
            s_w[ci][k][p] = make_float2(wp[0], wp[CIN * 16]);
        }
        for (int i = tid; i < CHUNK * 66 * 66; i += 256) {
            int ci = i / 4356, r = i % 4356, yy = r / 66, xx = r % 66;
            int gy = 2 * y0 - 1 + yy, gx = 2 * x0 - 1 + xx;
            float v = 0.f;
            if ((unsigned)gy < (unsigned)HIN && (unsigned)gx < (unsigned)HIN)
                v = ip[(size_t)(cc + ci) * HIN * HIN + gy * HIN + gx];
            s_in[ci][yy][xx] = v;
        }
        __syncthreads();

        #pragma unroll 1
        for (int ci = 0; ci < CHUNK; ci++) {
            #pragma unroll
            for (int k = 0; k < 16; k++) {
                const int ky = k / 4, kx = k % 4;
                const ull* wq = reinterpret_cast<const ull*>(&s_w[ci][k][0]);
                ull wv0 = wq[0], wv1 = wq[1], wv2 = wq[2], wv3 = wq[3];
                #pragma unroll
                for (int py = 0; py < 2; py++)
                    #pragma unroll
                    for (int px = 0; px < 2; px++) {
                        ull inp = pk2(s_in[ci][4 * ty + 2 * py + ky][4 * tx + 2 * px + kx]);
                        fma2(acc[py][px][0], inp, wv0);
                        fma2(acc[py][px][1], inp, wv1);
                        fma2(acc[py][px][2], inp, wv2);
                        fma2(acc[py][px][3], inp, wv3);
                    }
            }
        }
    }

    #pragma unroll
    for (int p = 0; p < 4; p++) {
        const int co = cg * 8 + 2 * p;
        const float b0 = b[co], b1 = b[co + 1];
        float* o0 = out + ((size_t)n * COUT + co) * HOUT * HOUT;
        float* o1 = o0 + HOUT * HOUT;
        #pragma unroll
        for (int py = 0; py < 2; py++)
            #pragma unroll
            for (int px = 0; px < 2; px++) {
                float2 v = up2(acc[py][px][p]);
                float r0 = __fadd_rn(v.x, b0), r1 = __fadd_rn(v.y, b1);
                if (RELU_OUT) { r0 = fmaxf(r0, 0.f); r1 = fmaxf(r1, 0.f); }
                int off = (y0 + 2 * ty + py) * HOUT + x0 + 2 * tx + px;
                o0[off] = r0;
                o1[off] = r1;
            }
    }
}

// ---------------------------------------------------------------------------
// conv 4x4, stride 2, pad 1 (legacy scalar; used for CIN=3 first layer).
// ---------------------------------------------------------------------------
template<int CIN, int COUT, int HOUT, bool RELU_OUT>
__global__ void __launch_bounds__(256) conv4s2_k(const float* __restrict__ in,
                                                 const float* __restrict__ w,
                                                 const float* __restrict__ b,
                                                 float* __restrict__ out)
{
    constexpr int HIN = HOUT * 2;
    constexpr int COG = COUT / 4;
    __shared__ float s_in[66][67];
    __shared__ float s_w[4][CIN][16];

    const int tid = threadIdx.x;
    const int tx = tid & 15, ty = tid >> 4;
    const int x0 = blockIdx.x * 32, y0 = blockIdx.y * 32;
    const int n  = blockIdx.z / COG;
    const int cg = blockIdx.z % COG;

    for (int i = tid; i < 4 * CIN * 16; i += 256) {
        int co = i / (CIN * 16), r = i % (CIN * 16);
        s_w[co][r / 16][r % 16] = w[(size_t)(cg * 4 + co) * CIN * 16 + r];
    }

    float acc[2][2][4];
    #pragma unroll
    for (int py = 0; py < 2; py++)
        #pragma unroll
        for (int px = 0; px < 2; px++)
            #pragma unroll
            for (int co = 0; co < 4; co++)
                acc[py][px][co] = 0.f;

    const float* ip = in + (size_t)n * CIN * HIN * HIN;
    for (int ci = 0; ci < CIN; ci++) {
        __syncthreads();
        const float* p = ip + (size_t)ci * HIN * HIN;
        for (int i = tid; i < 66 * 66; i += 256) {
            int yy = i / 66, xx = i % 66;
            int gy = 2 * y0 - 1 + yy, gx = 2 * x0 - 1 + xx;
            float v = 0.f;
            if ((unsigned)gy < (unsigned)HIN && (unsigned)gx < (unsigned)HIN)
                v = p[gy * HIN + gx];
            s_in[yy][xx] = v;
        }
        __syncthreads();
        #pragma unroll
        for (int py = 0; py < 2; py++)
            #pragma unroll
            for (int px = 0; px < 2; px++) {
                const int ly = ty + 16 * py, lx = tx + 16 * px;
                #pragma unroll
                for (int ky = 0; ky < 4; ky++)
                    #pragma unroll
                    for (int kx = 0; kx < 4; kx++) {
                        float v = s_in[2 * ly + ky][2 * lx + kx];
                        #pragma unroll
                        for (int co = 0; co < 4; co++)
                            acc[py][px][co] = fmaf(v, s_w[co][ci][ky * 4 + kx], acc[py][px][co]);
                    }
            }
    }

    #pragma unroll
    for (int co = 0; co < 4; co++) {
        float bias = b[cg * 4 + co];
        float* op = out + ((size_t)n * COUT + cg * 4 + co) * HOUT * HOUT;
        #pragma unroll
        for (int py = 0; py < 2; py++)
            #pragma unroll
            for (int px = 0; px < 2; px++) {
                float v = __fadd_rn(acc[py][px][co], bias);
                if (RELU_OUT) v = fmaxf(v, 0.f);
                op[(y0 + ty + 16 * py) * HOUT + x0 + tx + 16 * px] = v;
            }
    }
}

// ---------------------------------------------------------------------------
// conv 1x1 at 64x64, f32x2. Thread: 4 px (float4) x 8 cout.
// ---------------------------------------------------------------------------
template<int CIN, int COUT, bool RELU_IN, bool RESID>
__global__ void __launch_bounds__(256) conv1x1v2_k(const float* __restrict__ in,
                                                   const float* __restrict__ w,
                                                   const float* __restrict__ b,
                                                   float* __restrict__ out,
                                                   const float* __restrict__ resid)
{
    constexpr int COG = COUT / 8;
    __shared__ float2 s_w[CIN][4];
    const int tid = threadIdx.x;
    const int n  = blockIdx.z / COG;
    const int cg = blockIdx.z % COG;

    for (int i = tid; i < CIN * 4; i += 256) {
        int ci = i / 4, p = i % 4;
        s_w[ci][p] = make_float2(w[(size_t)(cg * 8 + 2 * p) * CIN + ci],
                                 w[(size_t)(cg * 8 + 2 * p + 1) * CIN + ci]);
    }
    __syncthreads();

    const int px0 = blockIdx.x * 1024 + tid * 4;
    const float* ip = in + (size_t)n * CIN * 4096 + px0;

    ull acc[4][4];
    #pragma unroll
    for (int j = 0; j < 4; j++)
        #pragma unroll
        for (int p = 0; p < 4; p++)
            acc[j][p] = 0ull;

    #pragma unroll 2
    for (int ci = 0; ci < CIN; ci++) {
        float4 v4 = *(const float4*)(ip + (size_t)ci * 4096);
        if (RELU_IN) {
            v4.x = fmaxf(v4.x, 0.f); v4.y = fmaxf(v4.y, 0.f);
            v4.z = fmaxf(v4.z, 0.f); v4.w = fmaxf(v4.w, 0.f);
        }
        ull i0 = pk2(v4.x), i1 = pk2(v4.y), i2 = pk2(v4.z), i3 = pk2(v4.w);
        const ull* wq = reinterpret_cast<const ull*>(&s_w[ci][0]);
        ull w0 = wq[0], w1 = wq[1], w2 = wq[2], w3 = wq[3];
        fma2(acc[0][0], i0, w0); fma2(acc[0][1], i0, w1); fma2(acc[0][2], i0, w2); fma2(acc[0][3], i0, w3);
        fma2(acc[1][0], i1, w0); fma2(acc[1][1], i1, w1); fma2(acc[1][2], i1, w2); fma2(acc[1][3], i1, w3);
        fma2(acc[2][0], i2, w0); fma2(acc[2][1], i2, w1); fma2(acc[2][2], i2, w2); fma2(acc[2][3], i2, w3);
        fma2(acc[3][0], i3, w0); fma2(acc[3][1], i3, w1); fma2(acc[3][2], i3, w2); fma2(acc[3][3], i3, w3);
    }

    #pragma unroll
    for (int p = 0; p < 4; p++) {
        const int co = cg * 8 + 2 * p;
        const float b0 = b[co], b1 = b[co + 1];
        float* o0 = out + ((size_t)n * COUT + co) * 4096 + px0;
        float* o1 = o0 + 4096;
        float4 r0, r1;
        float2 v0 = up2(acc[0][p]), v1 = up2(acc[1][p]), v2 = up2(acc[2][p]), v3 = up2(acc[3][p]);
        r0.x = __fadd_rn(v0.x, b0); r0.y = __fadd_rn(v1.x, b0);
        r0.z = __fadd_rn(v2.x, b0); r0.w = __fadd_rn(v3.x, b0);
        r1.x = __fadd_rn(v0.y, b1); r1.y = __fadd_rn(v1.y, b1);
        r1.z = __fadd_rn(v2.y, b1); r1.w = __fadd_rn(v3.y, b1);
        if (RESID) {
            const float* q0 = resid + ((size_t)n * COUT + co) * 4096 + px0;
            float4 s0 = *(const float4*)q0;
            float4 s1 = *(const float4*)(q0 + 4096);
            r0.x = __fadd_rn(s0.x, r0.x); r0.y = __fadd_rn(s0.y, r0.y);
            r0.z = __fadd_rn(s0.z, r0.z); r0.w = __fadd_rn(s0.w, r0.w);
            r1.x = __fadd_rn(s1.x, r1.x); r1.y = __fadd_rn(s1.y, r1.y);
            r1.z = __fadd_rn(s1.z, r1.z); r1.w = __fadd_rn(s1.w, r1.w);
        }
        *(float4*)o0 = r0;
        *(float4*)o1 = r1;
    }
}

// ---------------------------------------------------------------------------
// deconv1 k=4 s=2 p=1 (64x64 -> 128x128, CIN->COUT=64), f32x2.
// Tile out 32(y)x64(x); thread: 2x4 px (spacing 16), 8 cout. RELU in+out.
// Weight (Cin, Cout, 4, 4). Tap order per pixel: (ci, a, c2) as in R2.
// ---------------------------------------------------------------------------
template<int CIN>
__global__ void __launch_bounds__(256) deconv1v2_k(const float* __restrict__ in,
                                                   const float* __restrict__ w,
                                                   const float* __restrict__ b,
                                                   float* __restrict__ out)
{
    constexpr int COUT = 64, HIN = 64, HOUT = 128;
    constexpr int COG = COUT / 8;
    constexpr int CHUNK = 8;
    __shared__ float  s_in[CHUNK][18][36];
    __shared__ float2 s_w[CHUNK][16][4];

    const int tid = threadIdx.x;
    const int tx = tid & 15, ty = tid >> 4;
    const int x0 = blockIdx.x * 64, y0 = blockIdx.y * 32;
    const int n  = blockIdx.z / COG;
    const int cg = blockIdx.z % COG;

    ull acc[2][4][4];
    #pragma unroll
    for (int py = 0; py < 2; py++)
        #pragma unroll
        for (int qx = 0; qx < 4; qx++)
            #pragma unroll
            for (int p = 0; p < 4; p++)
                acc[py][qx][p] = 0ull;

    const int iyb = y0 / 2 - 1, ixb = x0 / 2 - 1;
    const float* ip = in + (size_t)n * CIN * HIN * HIN;

    // all thread pixels share tap parity (spacing 16 is even)
    const int ky0 = (ty + 1) & 1, kx0 = (tx + 1) & 1;

    #pragma unroll 1
    for (int cc = 0; cc < CIN; cc += CHUNK) {
        __syncthreads();
        for (int i = tid; i < CHUNK * 16 * 4; i += 256) {
            int ci = i / 64, r = i % 64, k = r / 4, p = r % 4;
            const float* wp = w + ((size_t)(cc + ci) * COUT + cg * 8 + 2 * p) * 16 + k;
            s_w[ci][k][p] = make_float2(wp[0], wp[16]);
        }
        for (int i = tid; i < CHUNK * 18 * 34; i += 256) {
            int ci = i / 612, r = i % 612, yy = r / 34, xx = r % 34;
            int gy = iyb + yy, gx = ixb + xx;
            float v = 0.f;
            if ((unsigned)gy < (unsigned)HIN && (unsigned)gx < (unsigned)HIN)
                v = ip[(size_t)(cc + ci) * HIN * HIN + gy * HIN + gx];
            v = fmaxf(v, 0.f);   // res_stack final relu
            s_in[ci][yy][xx] = v;
        }
        __syncthreads();

        #pragma unroll 1
        for (int ci = 0; ci < CHUNK; ci++) {
            #pragma unroll
            for (int a = 0; a < 2; a++) {
                const int ky = ky0 + 2 * a;
                #pragma unroll
                for (int c2 = 0; c2 < 2; c2++) {
                    const int kx = kx0 + 2 * c2;
                    const ull* wq = reinterpret_cast<const ull*>(&s_w[ci][ky * 4 + kx][0]);
                    ull wv0 = wq[0], wv1 = wq[1], wv2 = wq[2], wv3 = wq[3];
                    #pragma unroll
                    for (int py = 0; py < 2; py++) {
                        const int ly = ty + 16 * py;
                        const int iyl = ((ly + 1 - ky) >> 1) + 1;
                        #pragma unroll
                        for (int qx = 0; qx < 4; qx++) {
                            const int lx = tx + 16 * qx;
                            const int ixl = ((lx + 1 - kx) >> 1) + 1;
                            ull inp = pk2(s_in[ci][iyl][ixl]);
                            fma2(acc[py][qx][0], inp, wv0);
                            fma2(acc[py][qx][1], inp, wv1);
                            fma2(acc[py][qx][2], inp, wv2);
                            fma2(acc[py][qx][3], inp, wv3);
                        }
                    }
                }
            }
        }
    }

    // NOTE: tap accumulation order per pixel above is (ci, a, c2) — identical
    // chain order to the R2 kernel (weights were hoisted, operands unchanged).
    #pragma unroll
    for (int p = 0; p < 4; p++) {
        const int co = cg * 8 + 2 * p;
        const float b0 = b[co], b1 = b[co + 1];
        float* o0 = out + ((size_t)n * COUT + co) * HOUT * HOUT;
        float* o1 = o0 + HOUT * HOUT;
        #pragma unroll
        for (int py = 0; py < 2; py++)
            #pragma unroll
            for (int qx = 0; qx < 4; qx++) {
                float2 v = up2(acc[py][qx][p]);
                float r0 = fmaxf(__fadd_rn(v.x, b0), 0.f);
                float r1 = fmaxf(__fadd_rn(v.y, b1), 0.f);
                int off = (y0 + ty + 16 * py) * HOUT + x0 + tx + 16 * qx;
                o0[off] = r0;
                o1[off] = r1;
            }
    }
}

// ---------------------------------------------------------------------------
// Legacy scalar deconv (used for final 64->3 layer with tanh).
// ---------------------------------------------------------------------------
template<int CIN, int COUT, int CO_T, int HIN, bool RELU_IN, int ACT>
__global__ void __launch_bounds__(256) deconv_k(const float* __restrict__ in,
                                                const float* __restrict__ w,
                                                const float* __restrict__ b,
                                                float* __restrict__ out)
{
    constexpr int HOUT = HIN * 2;
    constexpr int COG = COUT / CO_T;
    __shared__ float s_in[18][19];
    __shared__ float s_w[CO_T][CIN][16];

    const int tid = threadIdx.x;
    const int tx = tid & 15, ty = tid >> 4;
    const int x0 = blockIdx.x * 32, y0 = blockIdx.y * 32;
    const int n  = blockIdx.z / COG;
    const int cg = blockIdx.z % COG;

    for (int i = tid; i < CO_T * CIN * 16; i += 256) {
        int co = i / (CIN * 16), r = i % (CIN * 16);
        int ci = r / 16, k = r % 16;
        s_w[co][ci][k] = w[((size_t)ci * COUT + cg * CO_T + co) * 16 + k];
    }

    float acc[2][2][CO_T];
    #pragma unroll
    for (int py = 0; py < 2; py++)
        #pragma unroll
        for (int px = 0; px < 2; px++)
            #pragma unroll
            for (int co = 0; co < CO_T; co++)
                acc[py][px][co] = 0.f;

    const int iyb = y0 / 2 - 1, ixb = x0 / 2 - 1;
    const float* ip = in + (size_t)n * CIN * HIN * HIN;

    for (int ci = 0; ci < CIN; ci++) {
        __syncthreads();
        const float* p = ip + (size_t)ci * HIN * HIN;
        for (int i = tid; i < 18 * 18; i += 256) {
            int yy = i / 18, xx = i % 18;
            int gy = iyb + yy, gx = ixb + xx;
            float v = 0.f;
            if ((unsigned)gy < (unsigned)HIN && (unsigned)gx < (unsigned)HIN)
                v = p[gy * HIN + gx];
            if (RELU_IN) v = fmaxf(v, 0.f);
            s_in[yy][xx] = v;
        }
        __syncthreads();
        #pragma unroll
        for (int py = 0; py < 2; py++)
            #pragma unroll
            for (int px = 0; px < 2; px++) {
                const int ly = ty + 16 * py, lx = tx + 16 * px;
                const int ky0 = (ly + 1) & 1, kx0 = (lx + 1) & 1;
                #pragma unroll
                for (int a = 0; a < 2; a++) {
                    const int ky = ky0 + 2 * a;
                    const int iyl = ((ly + 1 - ky) >> 1) + 1;
                    #pragma unroll
                    for (int c2 = 0; c2 < 2; c2++) {
                        const int kx = kx0 + 2 * c2;
                        const int ixl = ((lx + 1 - kx) >> 1) + 1;
                        float v = s_in[iyl][ixl];
                        #pragma unroll
                        for (int co = 0; co < CO_T; co++)
                            acc[py][px][co] = fmaf(v, s_w[co][ci][ky * 4 + kx], acc[py][px][co]);
                    }
                }
            }
    }

    #pragma unroll
    for (int co = 0; co < CO_T; co++) {
        float bias = b[cg * CO_T + co];
        float* op = out + ((size_t)n * COUT + cg * CO_T + co) * HOUT * HOUT;
        #pragma unroll
        for (int py = 0; py < 2; py++)
            #pragma unroll
            for (int px = 0; px < 2; px++) {
                float v = __fadd_rn(acc[py][px][co], bias);
                if (ACT == 1) v = fmaxf(v, 0.f);
                if (ACT == 2) v = tanhf(v);
                op[(y0 + ty + 16 * py) * HOUT + x0 + tx + 16 * px] = v;
            }
    }
}

// ---------------------------------------------------------------------------
// VQ (codebook norms, argmin + loss, finalize)
// ---------------------------------------------------------------------------
__global__ void cnorm_k(const float* __restrict__ cb, float* __restrict__ cn)
{
    int c = blockIdx.x * 256 + threadIdx.x;
    if (c < 512) {
        float s = 0.f;
        for (int d = 0; d < 64; d++) {
            float v = cb[c * 64 + d];
            s = __fadd_rn(s, __fmul_rn(v, v));
        }
        cn[c] = s;
    }
}

__global__ void zero_loss_k(double* loss) { *loss = 0.0; }

__global__ void __launch_bounds__(256) vq_k(const float* __restrict__ z,
                                            const float* __restrict__ cb,
                                            const float* __restrict__ cn,
                                            float* __restrict__ q,
                                            double* __restrict__ loss)
{
    __shared__ float s_cT[64][128];   // [d][c] for one 128-code chunk
    __shared__ float s_n[128];
    __shared__ double s_red[256];

    const int tid = threadIdx.x;
    const int vec = blockIdx.x * 256 + tid;
    const int n = vec >> 12, px = vec & 4095;
    const float* zp = z + (size_t)n * 64 * 4096 + px;

    float zr[64];
    #pragma unroll
    for (int d = 0; d < 64; d++) zr[d] = zp[(size_t)d * 4096];

    float sumz2 = 0.f;
    #pragma unroll
    for (int d = 0; d < 64; d++)
        sumz2 = __fadd_rn(sumz2, __fmul_rn(zr[d], zr[d]));

    float best = 3.4e38f;
    int bi = 0;

    for (int ch = 0; ch < 4; ch++) {
        __syncthreads();
        for (int i = tid; i < 128 * 64; i += 256) {
            int c = i >> 6, d = i & 63;
            s_cT[d][c] = cb[(size_t)(ch * 128 + c) * 64 + d];
        }
        if (tid < 128) s_n[tid] = cn[ch * 128 + tid];
        __syncthreads();

        for (int c0 = 0; c0 < 128; c0 += 8) {
            ull a[4];
            #pragma unroll
            for (int j = 0; j < 4; j++) a[j] = 0ull;
            #pragma unroll
            for (int d = 0; d < 64; d++) {
                ull zv = pk2(zr[d]);
                const ulonglong2* cq = reinterpret_cast<const ulonglong2*>(&s_cT[d][c0]);
                ulonglong2 c01 = cq[0], c23 = cq[1];
                fma2(a[0], zv, c01.x);
                fma2(a[1], zv, c01.y);
                fma2(a[2], zv, c23.x);
                fma2(a[3], zv, c23.y);
            }
            #pragma unroll
            for (int j = 0; j < 4; j++) {
                float2 dots = up2(a[j]);
                int c = ch * 128 + c0 + 2 * j;
                float t0 = __fadd_rn(sumz2, -2.f * dots.x);
                float d0 = __fadd_rn(t0, s_n[c0 + 2 * j]);
                if (d0 < best) { best = d0; bi = c; }
                float t1 = __fadd_rn(sumz2, -2.f * dots.y);
                float d1 = __fadd_rn(t1, s_n[c0 + 2 * j + 1]);
                if (d1 < best) { best = d1; bi = c + 1; }
            }
        }
    }

    const float* cp = cb + (size_t)bi * 64;
    float* qp = q + (size_t)n * 64 * 4096 + px;
    double sum = 0.0;
    #pragma unroll
    for (int d = 0; d < 64; d++) {
        float qv = __ldg(cp + d);
        float df = __fadd_rn(qv, -zr[d]);
        sum += (double)df * (double)df;
        qp[(size_t)d * 4096] = __fadd_rn(zr[d], df);   // straight-through
    }

    s_red[tid] = sum;
    __syncthreads();
    for (int s = 128; s > 0; s >>= 1) {
        if (tid < s) s_red[tid] += s_red[tid + s];
        __syncthreads();
    }
    if (tid == 0) atomicAdd(loss, s_red[0]);
}

__global__ void finalize_k(const double* __restrict__ loss, float* __restrict__ out, int idx)
{
    out[idx] = (float)((*loss) * 1.25 / 8388608.0);
}

// ---------------------------------------------------------------------------
// Host orchestration
// ---------------------------------------------------------------------------
extern "C" void kernel_launch(void* const* d_in, const int* in_sizes, int n_in,
                              void* d_out, int out_size)
{
    const float* x    = (const float*)d_in[0];
    const float* ew1  = (const float*)d_in[1];
    const float* eb1  = (const float*)d_in[2];
    const float* ew2  = (const float*)d_in[3];
    const float* eb2  = (const float*)d_in[4];
    const float* ew3  = (const float*)d_in[5];
    const float* eb3  = (const float*)d_in[6];
    const float* erw1 = (const float*)d_in[7];
    const float* erb1 = (const float*)d_in[8];
    const float* erw2 = (const float*)d_in[9];
    const float* erb2 = (const float*)d_in[10];
    const float* pvqw = (const float*)d_in[11];
    const float* pvqb = (const float*)d_in[12];
    const float* cb   = (const float*)d_in[13];
    const float* dw1  = (const float*)d_in[14];
    const float* db1  = (const float*)d_in[15];
    const float* drw1 = (const float*)d_in[16];
    const float* drb1 = (const float*)d_in[17];
    const float* drw2 = (const float*)d_in[18];
    const float* drb2 = (const float*)d_in[19];
    const float* t1w  = (const float*)d_in[20];
    const float* t1b  = (const float*)d_in[21];
    const float* t2w  = (const float*)d_in[22];
    const float* t2b  = (const float*)d_in[23];
    float* out = (float*)d_out;

    float *A, *B, *C, *T, *Z, *Q, *CN;
    double* L;
    cudaGetSymbolAddress((void**)&A, g_A);
    cudaGetSymbolAddress((void**)&B, g_B);
    cudaGetSymbolAddress((void**)&C, g_C);
    cudaGetSymbolAddress((void**)&T, g_T);
    cudaGetSymbolAddress((void**)&Z, g_Z);
    cudaGetSymbolAddress((void**)&Q, g_Q);
    cudaGetSymbolAddress((void**)&CN, g_CN);
    cudaGetSymbolAddress((void**)&L, g_LOSS);

    // Encoder
    conv4s2_k<3, 64, 128, true><<<dim3(4, 4, NB * 16), 256>>>(x, ew1, eb1, A);
    conv4v2_k<64, 128, 64, true><<<dim3(2, 2, NB * 16), 256>>>(A, ew2, eb2, B);
    conv3v2_k<128, 128, false><<<dim3(2, 2, NB * 16), 256>>>(B, ew3, eb3, C);
    for (int i = 0; i < 2; i++) {
        conv3v2_k<128, 32, true><<<dim3(2, 2, NB * 4), 256>>>(
            C, erw1 + (size_t)i * 32 * 128 * 9, erb1 + i * 32, T);
        conv1x1v2_k<32, 128, true, true><<<dim3(4, 1, NB * 16), 256>>>(
            T, erw2 + (size_t)i * 128 * 32, erb2 + i * 128, C, C);
    }
    conv1x1v2_k<128, 64, true, false><<<dim3(4, 1, NB * 8), 256>>>(C, pvqw, pvqb, Z, nullptr);

    // VQ
    zero_loss_k<<<1, 1>>>(L);
    cnorm_k<<<2, 256>>>(cb, CN);
    vq_k<<<512, 256>>>(Z, cb, CN, Q, L);

    // Decoder
    conv3v2_k<64, 128, false><<<dim3(2, 2, NB * 16), 256>>>(Q, dw1, db1, B);
    for (int i = 0; i < 2; i++) {
        conv3v2_k<128, 32, true><<<dim3(2, 2, NB * 4), 256>>>(
            B, drw1 + (size_t)i * 32 * 128 * 9, drb1 + i * 32, T);
        conv1x1v2_k<32, 128, true, true><<<dim3(4, 1, NB * 16), 256>>>(
            T, drw2 + (size_t)i * 128 * 32, drb2 + i * 128, B, B);
    }
    deconv1v2_k<128><<<dim3(2, 4, NB * 8), 256>>>(B, t1w, t1b, A);
    deconv_k<64, 3, 3, 128, false, 2><<<dim3(8, 8, NB), 256>>>(A, t2w, t2b, out);

    if (out_size > 32 * 3 * 256 * 256)
        finalize_k<<<1, 1>>>(L, out, out_size - 1);
}